// round 10
// baseline (speedup 1.0000x reference)
#include <cuda_runtime.h>
#include <cuda_bf16.h>
#include <cstdint>

#define DINL __device__ __forceinline__
#define MROWS 8192
#define NCOLS 4096
#define KDIM  4096

// ---------------- scratch ----------------
__device__ __align__(1024) int8_t g_qx8[(size_t)MROWS * KDIM]; // [M][K] int8
__device__ __align__(1024) int8_t g_qk8[(size_t)NCOLS * KDIM]; // [F][D] int8 (transposed weight)
__device__ float    g_sx[MROWS];
__device__ unsigned g_skbits[NCOLS];   // zero at module load; atomicMax idempotent across replays
__device__ float    g_sks[NCOLS];
__device__ float    g_bq[NCOLS];

DINL float q8(float v, float s) {
    float t = __fdiv_rn(v, s);
    return rintf(fminf(fmaxf(t, -127.0f), 127.0f));
}
DINL unsigned u8(float f) { return (unsigned)((int)f) & 0xffu; }
DINL float blockAbsMax256(float v, float* sred) {
    #pragma unroll
    for (int o = 16; o; o >>= 1) v = fmaxf(v, __shfl_xor_sync(0xffffffffu, v, o));
    if ((threadIdx.x & 31) == 0) sred[threadIdx.x >> 5] = v;
    __syncthreads();
    if (threadIdx.x == 0) {
        float m = sred[0];
        #pragma unroll
        for (int k = 1; k < 8; k++) m = fmaxf(m, sred[k]);
        sred[8] = m;
    }
    __syncthreads();
    return sred[8];
}

// ---------------- quantize X (blocks 0..8191) + bias int16 fake-quant (block 8192) ----------------
__global__ void __launch_bounds__(256) quantX_kernel(const float* __restrict__ x,
                                                     const float* __restrict__ bias) {
    __shared__ float sred[9];
    int t = threadIdx.x;
    if (blockIdx.x == MROWS) {
        float v[16], am = 0.f;
        #pragma unroll
        for (int i = 0; i < 16; i++) { v[i] = bias[t * 16 + i]; am = fmaxf(am, fabsf(v[i])); }
        am = blockAbsMax256(am, sred);
        float sc = (am == 0.f) ? 1.0f : __fdiv_rn(am, 32767.0f);
        #pragma unroll
        for (int i = 0; i < 16; i++) {
            float q = rintf(fminf(fmaxf(__fdiv_rn(v[i], sc), -32767.0f), 32767.0f));
            g_bq[t * 16 + i] = q * sc;
        }
        return;
    }
    int m = blockIdx.x;
    const float4* xr = (const float4*)(x + (size_t)m * KDIM);
    float4 v[4];
    float am = 0.f;
    #pragma unroll
    for (int i = 0; i < 4; i++) {
        v[i] = xr[t * 4 + i];
        am = fmaxf(am, fmaxf(fmaxf(fabsf(v[i].x), fabsf(v[i].y)),
                             fmaxf(fabsf(v[i].z), fabsf(v[i].w))));
    }
    am = blockAbsMax256(am, sred);
    float sc = (am == 0.f) ? 1.0f : __fdiv_rn(am, 127.0f);
    if (t == 0) g_sx[m] = sc;
    uint4 w;
    w.x = u8(q8(v[0].x,sc)) | (u8(q8(v[0].y,sc))<<8) | (u8(q8(v[0].z,sc))<<16) | (u8(q8(v[0].w,sc))<<24);
    w.y = u8(q8(v[1].x,sc)) | (u8(q8(v[1].y,sc))<<8) | (u8(q8(v[1].z,sc))<<16) | (u8(q8(v[1].w,sc))<<24);
    w.z = u8(q8(v[2].x,sc)) | (u8(q8(v[2].y,sc))<<8) | (u8(q8(v[2].z,sc))<<16) | (u8(q8(v[2].w,sc))<<24);
    w.w = u8(q8(v[3].x,sc)) | (u8(q8(v[3].y,sc))<<8) | (u8(q8(v[3].z,sc))<<16) | (u8(q8(v[3].w,sc))<<24);
    *(uint4*)(g_qx8 + (size_t)m * KDIM + t * 16) = w;
}

// ---------------- weight column absmax (axis 0) ----------------
__global__ void __launch_bounds__(256) colmax_kernel(const float* __restrict__ kern) {
    int f  = (blockIdx.x & 15) * 256 + threadIdx.x;
    int d0 = (blockIdx.x >> 4) * 128;
    float am = 0.f;
    const float* p = kern + (size_t)d0 * NCOLS + f;
    #pragma unroll 4
    for (int d = 0; d < 128; d++) am = fmaxf(am, fabsf(p[(size_t)d * NCOLS]));
    atomicMax(&g_skbits[f], __float_as_uint(am));
}

// ---------------- quantize + transpose weights -> int8 [F][D]; also emit g_sks ----------------
__global__ void __launch_bounds__(256) quantW_kernel(const float* __restrict__ kern) {
    int nt = blockIdx.x >> 6, kt = blockIdx.x & 63;
    int f0 = nt * 128, d0 = kt * 64;
    int t = threadIdx.x, r = t >> 1, h = t & 1;
    float am = __uint_as_float(g_skbits[f0 + r]);
    float sc = (am == 0.f) ? 1.0f : __fdiv_rn(am, 127.0f);
    if (kt == 0 && h == 0) g_sks[f0 + r] = sc;
    const float* src = kern + (size_t)(d0 + h * 32) * NCOLS + f0 + r;
    unsigned w[8];
    #pragma unroll
    for (int j = 0; j < 8; j++) {
        unsigned b0 = u8(q8(src[(size_t)(4*j+0) * NCOLS], sc));
        unsigned b1 = u8(q8(src[(size_t)(4*j+1) * NCOLS], sc));
        unsigned b2 = u8(q8(src[(size_t)(4*j+2) * NCOLS], sc));
        unsigned b3 = u8(q8(src[(size_t)(4*j+3) * NCOLS], sc));
        w[j] = b0 | (b1 << 8) | (b2 << 16) | (b3 << 24);
    }
    uint4* dst = (uint4*)(g_qk8 + (size_t)(f0 + r) * KDIM + d0 + h * 32);
    dst[0] = make_uint4(w[0], w[1], w[2], w[3]);
    dst[1] = make_uint4(w[4], w[5], w[6], w[7]);
}

// =========== GEMM: hybrid tensor(IMMA) + dp4a, 128x128 tile, dual-pipe ===========
#define STAGES 4
#define STAGE_BYTES 16384
#define SMEM_TOT (STAGES * STAGE_BYTES)

DINL uint32_t smem_u32(const void* p) {
    uint32_t a;
    asm("{ .reg .u64 t; cvta.to.shared.u64 t, %1; cvt.u32.u64 %0, t; }" : "=r"(a) : "l"(p));
    return a;
}
DINL void cp16(uint32_t dst, const void* src) {
    asm volatile("cp.async.cg.shared.global [%0], [%1], 16;" :: "r"(dst), "l"(src) : "memory");
}
DINL void ldmx4(uint32_t* r, uint32_t a) {
    asm volatile("ldmatrix.sync.aligned.m8n8.x4.shared.b16 {%0,%1,%2,%3}, [%4];"
        : "=r"(r[0]), "=r"(r[1]), "=r"(r[2]), "=r"(r[3]) : "r"(a));
}
DINL void mma8(int* c, const uint32_t* a, const uint32_t* b) {
    asm volatile("mma.sync.aligned.m16n8k32.row.col.s32.s8.s8.s32 "
        "{%0,%1,%2,%3}, {%4,%5,%6,%7}, {%8,%9}, {%0,%1,%2,%3};"
        : "+r"(c[0]), "+r"(c[1]), "+r"(c[2]), "+r"(c[3])
        : "r"(a[0]), "r"(a[1]), "r"(a[2]), "r"(a[3]), "r"(b[0]), "r"(b[1]));
}

DINL void load_stage(uint32_t sb, int tm, int tn, int kt, int st, int tid) {
    uint32_t sA = sb + st * STAGE_BYTES;
    uint32_t sB = sA + 8192;
    #pragma unroll
    for (int i = 0; i < 2; i++) {
        int idx = i * 256 + tid;
        int row = idx >> 2, w = idx & 3;
        uint32_t d = sA + row * 64 + ((w ^ ((row >> 1) & 3)) << 4);
        cp16(d, g_qx8 + (size_t)(tm * 128 + row) * KDIM + kt * 64 + w * 16);
    }
    #pragma unroll
    for (int i = 0; i < 2; i++) {
        int idx = i * 256 + tid;
        int row = idx >> 2, w = idx & 3;
        uint32_t d = sB + row * 64 + ((w ^ ((row >> 1) & 3)) << 4);
        cp16(d, g_qk8 + (size_t)(tn * 128 + row) * KDIM + kt * 64 + w * 16);
    }
    asm volatile("cp.async.commit_group;" ::: "memory");
}

// 64 dp4a: rows i0..i0+3 of this thread's dp4a tile, one 16B k-chunk
#define DP4A_GROUP(i0, sAoff, wc) do {                                          \
    _Pragma("unroll")                                                           \
    for (int i = (i0); i < (i0) + 4; i++) {                                     \
        int rowA = dAr + 4 * i;                                                 \
        uint4 aw = *(const uint4*)(smem + (sAoff) + rowA * 64                   \
                                   + (((wc) ^ ((rowA >> 1) & 3)) << 4));        \
        _Pragma("unroll")                                                       \
        for (int j = 0; j < 4; j++) {                                           \
            cd[i][j] = __dp4a((int)aw.x, (int)bw[j].x, cd[i][j]);               \
            cd[i][j] = __dp4a((int)aw.y, (int)bw[j].y, cd[i][j]);               \
            cd[i][j] = __dp4a((int)aw.z, (int)bw[j].z, cd[i][j]);               \
            cd[i][j] = __dp4a((int)aw.w, (int)bw[j].w, cd[i][j]);               \
        }                                                                       \
    } } while (0)

#define DP4A_BLOAD(sBoff, wc) do {                                              \
    _Pragma("unroll")                                                           \
    for (int j = 0; j < 4; j++) {                                               \
        int rowB = dBr + 8 * j;                                                 \
        bw[j] = *(const uint4*)(smem + (sBoff) + rowB * 64                      \
                                + (((wc) ^ ((rowB >> 1) & 3)) << 4));           \
    } } while (0)

__global__ void __launch_bounds__(256, 1) gemm8_kernel(float* __restrict__ out) {
    extern __shared__ char smem[];
    uint32_t sb = smem_u32(smem);
    int tid = threadIdx.x, lane = tid & 31, wid = tid >> 5;
    int wm = wid >> 1, wn = wid & 1;
    int tn = blockIdx.x & 31, tm = blockIdx.x >> 5;

    int ct[2][4][4];          // tensor accum: cols wn*64 + 0..31
    int cd[8][4];             // dp4a accum:   cols wn*64 + 32..63
    #pragma unroll
    for (int mb = 0; mb < 2; mb++)
        #pragma unroll
        for (int nb = 0; nb < 4; nb++)
            #pragma unroll
            for (int i = 0; i < 4; i++) ct[mb][nb][i] = 0;
    #pragma unroll
    for (int i = 0; i < 8; i++)
        #pragma unroll
        for (int j = 0; j < 4; j++) cd[i][j] = 0;

    load_stage(sb, tm, tn, 0, 0, tid);
    load_stage(sb, tm, tn, 1, 1, tid);
    load_stage(sb, tm, tn, 2, 2, tid);

    int aRow0 = wm * 32 + (lane & 7) + ((lane >> 3) & 1) * 8;
    int aWsel = (lane >> 4);
    int bRow0 = wn * 64 + ((lane >> 4) << 3) + (lane & 7);
    int bWsel = ((lane >> 3) & 1);
    int dAr = wm * 32 + (lane & 3);        // dp4a A rows: + 4*i
    int dBr = wn * 64 + 32 + (lane >> 2);  // dp4a B rows: + 8*j

    int st = 0;
    for (int kt = 0; kt < 64; kt++) {
        asm volatile("cp.async.wait_group %0;" :: "n"(2) : "memory");
        __syncthreads();
        if (kt + 3 < 64) {
            int st2 = st + 3; if (st2 >= STAGES) st2 -= STAGES;
            load_stage(sb, tm, tn, kt + 3, st2, tid);
        }
        int sAoff = st * STAGE_BYTES;
        int sBoff = sAoff + 8192;
        uint32_t sA = sb + sAoff, sB = sb + sBoff;
        #pragma unroll
        for (int ks = 0; ks < 2; ks++) {
            // tensor fragments
            uint32_t a[2][4];
            #pragma unroll
            for (int mb = 0; mb < 2; mb++) {
                int row = aRow0 + mb * 16;
                int w = 2 * ks + aWsel;
                ldmx4(a[mb], sA + row * 64 + ((w ^ ((row >> 1) & 3)) << 4));
            }
            uint32_t bt[4][2];
            #pragma unroll
            for (int p = 0; p < 2; p++) {
                int nrow = bRow0 + p * 16;
                int w = 2 * ks + bWsel;
                uint32_t r[4];
                ldmx4(r, sB + nrow * 64 + ((w ^ ((nrow >> 1) & 3)) << 4));
                bt[2*p][0] = r[0]; bt[2*p][1] = r[1];
                bt[2*p+1][0] = r[2]; bt[2*p+1][1] = r[3];
            }
            // interleave: 8 mma + 256 dp4a (2 chunks of 16B)
            uint4 bw[4];
            int wc0 = 2 * ks, wc1 = 2 * ks + 1;
            DP4A_BLOAD(sBoff, wc0);
            mma8(ct[0][0], a[0], bt[0]); mma8(ct[0][1], a[0], bt[1]);
            DP4A_GROUP(0, sAoff, wc0);
            mma8(ct[0][2], a[0], bt[2]); mma8(ct[0][3], a[0], bt[3]);
            DP4A_GROUP(4, sAoff, wc0);
            mma8(ct[1][0], a[1], bt[0]); mma8(ct[1][1], a[1], bt[1]);
            DP4A_BLOAD(sBoff, wc1);
            DP4A_GROUP(0, sAoff, wc1);
            mma8(ct[1][2], a[1], bt[2]); mma8(ct[1][3], a[1], bt[3]);
            DP4A_GROUP(4, sAoff, wc1);
        }
        if (++st == STAGES) st = 0;
    }

    // ---------------- epilogue ----------------
    // tensor half: cols tn*128 + wn*64 + 0..31
    int row0 = tm * 128 + wm * 32 + (lane >> 2);
    int ncol0 = tn * 128 + wn * 64 + (lane & 3) * 2;
    #pragma unroll
    for (int mb = 0; mb < 2; mb++) {
        #pragma unroll
        for (int half = 0; half < 2; half++) {
            int m = row0 + mb * 16 + half * 8;
            float sxv = g_sx[m];
            float* orow = out + (size_t)m * NCOLS + ncol0;
            #pragma unroll
            for (int nb = 0; nb < 4; nb++) {
                int n0 = ncol0 + nb * 8;
                float s0 = g_sks[n0],   s1 = g_sks[n0+1];
                float b0 = g_bq[n0],    b1 = g_bq[n0+1];
                float2 o;
                o.x = fmaf((float)ct[mb][nb][2*half],   sxv * s0, b0);
                o.y = fmaf((float)ct[mb][nb][2*half+1], sxv * s1, b1);
                *(float2*)(orow + nb * 8) = o;
            }
        }
    }
    // dp4a half: cols tn*128 + wn*64 + 32..63
    #pragma unroll
    for (int i = 0; i < 8; i++) {
        int m = tm * 128 + dAr + 4 * i;
        float sxv = g_sx[m];
        float* orow = out + (size_t)m * NCOLS;
        #pragma unroll
        for (int j = 0; j < 4; j++) {
            int n = tn * 128 + dBr + 8 * j;
            orow[n] = fmaf((float)cd[i][j], sxv * g_sks[n], g_bq[n]);
        }
    }
}

// ---------------- output requant (in place, per-row) ----------------
__global__ void __launch_bounds__(256) requant_kernel(float* __restrict__ out) {
    __shared__ float sred[9];
    int m = blockIdx.x, t = threadIdx.x;
    float4* row = (float4*)(out + (size_t)m * NCOLS);
    float4 v[4];
    float am = 0.f;
    #pragma unroll
    for (int i = 0; i < 4; i++) {
        v[i] = row[t * 4 + i];
        am = fmaxf(am, fmaxf(fmaxf(fabsf(v[i].x), fabsf(v[i].y)),
                             fmaxf(fabsf(v[i].z), fabsf(v[i].w))));
    }
    am = blockAbsMax256(am, sred);
    float sc = (am == 0.f) ? 1.0f : __fdiv_rn(am, 127.0f);
    #pragma unroll
    for (int i = 0; i < 4; i++) {
        v[i].x = q8(v[i].x, sc) * sc;
        v[i].y = q8(v[i].y, sc) * sc;
        v[i].z = q8(v[i].z, sc) * sc;
        v[i].w = q8(v[i].w, sc) * sc;
        row[t * 4 + i] = v[i];
    }
}

extern "C" void kernel_launch(void* const* d_in, const int* in_sizes, int n_in,
                              void* d_out, int out_size) {
    const float* x    = (const float*)d_in[0];
    const float* kern = (const float*)d_in[1];
    const float* bias = (const float*)d_in[2];
    float* out = (float*)d_out;
    cudaFuncSetAttribute(gemm8_kernel, cudaFuncAttributeMaxDynamicSharedMemorySize, SMEM_TOT);
    quantX_kernel<<<MROWS + 1, 256>>>(x, bias);   // launch 1
    colmax_kernel<<<512, 256>>>(kern);            // launch 2
    quantW_kernel<<<2048, 256>>>(kern);           // launch 3
    gemm8_kernel<<<2048, 256, SMEM_TOT>>>(out);   // launch 4  (ncu -s 5 -c 1 target)
    requant_kernel<<<8192, 256>>>(out);           // launch 5
}

// round 11
// speedup vs baseline: 1.4763x; 1.4763x over previous
#include <cuda_runtime.h>
#include <cuda_bf16.h>
#include <cstdint>

#define DINL __device__ __forceinline__
#define MROWS 8192
#define NCOLS 4096
#define KDIM  4096

// ---------------- scratch ----------------
__device__ __align__(1024) int8_t g_qx8[(size_t)MROWS * KDIM]; // [M][K] int8
__device__ __align__(1024) int8_t g_qk8[(size_t)NCOLS * KDIM]; // [F][D] int8 (transposed weight)
__device__ float    g_sx[MROWS];
__device__ unsigned g_skbits[NCOLS];   // zero at module load; atomicMax idempotent across replays
__device__ float    g_sks[NCOLS];
__device__ float    g_bq[NCOLS];

DINL float q8(float v, float s) {
    float t = __fdiv_rn(v, s);
    return rintf(fminf(fmaxf(t, -127.0f), 127.0f));
}
DINL unsigned u8(float f) { return (unsigned)((int)f) & 0xffu; }
DINL float blockAbsMax256(float v, float* sred) {
    #pragma unroll
    for (int o = 16; o; o >>= 1) v = fmaxf(v, __shfl_xor_sync(0xffffffffu, v, o));
    if ((threadIdx.x & 31) == 0) sred[threadIdx.x >> 5] = v;
    __syncthreads();
    if (threadIdx.x == 0) {
        float m = sred[0];
        #pragma unroll
        for (int k = 1; k < 8; k++) m = fmaxf(m, sred[k]);
        sred[8] = m;
    }
    __syncthreads();
    return sred[8];
}

// ---------------- quantize X (blocks 0..8191) + bias int16 fake-quant (block 8192) ----------------
__global__ void __launch_bounds__(256) quantX_kernel(const float* __restrict__ x,
                                                     const float* __restrict__ bias) {
    __shared__ float sred[9];
    int t = threadIdx.x;
    if (blockIdx.x == MROWS) {
        float v[16], am = 0.f;
        #pragma unroll
        for (int i = 0; i < 16; i++) { v[i] = bias[t * 16 + i]; am = fmaxf(am, fabsf(v[i])); }
        am = blockAbsMax256(am, sred);
        float sc = (am == 0.f) ? 1.0f : __fdiv_rn(am, 32767.0f);
        #pragma unroll
        for (int i = 0; i < 16; i++) {
            float q = rintf(fminf(fmaxf(__fdiv_rn(v[i], sc), -32767.0f), 32767.0f));
            g_bq[t * 16 + i] = q * sc;
        }
        return;
    }
    int m = blockIdx.x;
    const float4* xr = (const float4*)(x + (size_t)m * KDIM);
    float4 v[4];
    float am = 0.f;
    #pragma unroll
    for (int i = 0; i < 4; i++) {
        v[i] = xr[t * 4 + i];
        am = fmaxf(am, fmaxf(fmaxf(fabsf(v[i].x), fabsf(v[i].y)),
                             fmaxf(fabsf(v[i].z), fabsf(v[i].w))));
    }
    am = blockAbsMax256(am, sred);
    float sc = (am == 0.f) ? 1.0f : __fdiv_rn(am, 127.0f);
    if (t == 0) g_sx[m] = sc;
    uint4 w;
    w.x = u8(q8(v[0].x,sc)) | (u8(q8(v[0].y,sc))<<8) | (u8(q8(v[0].z,sc))<<16) | (u8(q8(v[0].w,sc))<<24);
    w.y = u8(q8(v[1].x,sc)) | (u8(q8(v[1].y,sc))<<8) | (u8(q8(v[1].z,sc))<<16) | (u8(q8(v[1].w,sc))<<24);
    w.z = u8(q8(v[2].x,sc)) | (u8(q8(v[2].y,sc))<<8) | (u8(q8(v[2].z,sc))<<16) | (u8(q8(v[2].w,sc))<<24);
    w.w = u8(q8(v[3].x,sc)) | (u8(q8(v[3].y,sc))<<8) | (u8(q8(v[3].z,sc))<<16) | (u8(q8(v[3].w,sc))<<24);
    *(uint4*)(g_qx8 + (size_t)m * KDIM + t * 16) = w;
}

// ---------------- weight column absmax (axis 0) ----------------
__global__ void __launch_bounds__(256) colmax_kernel(const float* __restrict__ kern) {
    int f  = (blockIdx.x & 15) * 256 + threadIdx.x;
    int d0 = (blockIdx.x >> 4) * 128;
    float am = 0.f;
    const float* p = kern + (size_t)d0 * NCOLS + f;
    #pragma unroll 4
    for (int d = 0; d < 128; d++) am = fmaxf(am, fabsf(p[(size_t)d * NCOLS]));
    atomicMax(&g_skbits[f], __float_as_uint(am));
}

// ---------------- quantize + transpose weights -> int8 [F][D]; also emit g_sks ----------------
__global__ void __launch_bounds__(256) quantW_kernel(const float* __restrict__ kern) {
    int nt = blockIdx.x >> 6, kt = blockIdx.x & 63;
    int f0 = nt * 128, d0 = kt * 64;
    int t = threadIdx.x, r = t >> 1, h = t & 1;
    float am = __uint_as_float(g_skbits[f0 + r]);
    float sc = (am == 0.f) ? 1.0f : __fdiv_rn(am, 127.0f);
    if (kt == 0 && h == 0) g_sks[f0 + r] = sc;
    const float* src = kern + (size_t)(d0 + h * 32) * NCOLS + f0 + r;
    unsigned w[8];
    #pragma unroll
    for (int j = 0; j < 8; j++) {
        unsigned b0 = u8(q8(src[(size_t)(4*j+0) * NCOLS], sc));
        unsigned b1 = u8(q8(src[(size_t)(4*j+1) * NCOLS], sc));
        unsigned b2 = u8(q8(src[(size_t)(4*j+2) * NCOLS], sc));
        unsigned b3 = u8(q8(src[(size_t)(4*j+3) * NCOLS], sc));
        w[j] = b0 | (b1 << 8) | (b2 << 16) | (b3 << 24);
    }
    uint4* dst = (uint4*)(g_qk8 + (size_t)(f0 + r) * KDIM + d0 + h * 32);
    dst[0] = make_uint4(w[0], w[1], w[2], w[3]);
    dst[1] = make_uint4(w[4], w[5], w[6], w[7]);
}

// ==== GEMM: warp-specialized tensor(IMMA cols 0-63) + dp4a (cols 64-127), 128x128 tile ====
#define STAGES 4
#define STAGE_BYTES 16384
#define SMEM_TOT (STAGES * STAGE_BYTES)

DINL uint32_t smem_u32(const void* p) {
    uint32_t a;
    asm("{ .reg .u64 t; cvta.to.shared.u64 t, %1; cvt.u32.u64 %0, t; }" : "=r"(a) : "l"(p));
    return a;
}
DINL void cp16(uint32_t dst, const void* src) {
    asm volatile("cp.async.cg.shared.global [%0], [%1], 16;" :: "r"(dst), "l"(src) : "memory");
}
DINL void ldmx4(uint32_t* r, uint32_t a) {
    asm volatile("ldmatrix.sync.aligned.m8n8.x4.shared.b16 {%0,%1,%2,%3}, [%4];"
        : "=r"(r[0]), "=r"(r[1]), "=r"(r[2]), "=r"(r[3]) : "r"(a));
}
DINL void mma8(int* c, const uint32_t* a, const uint32_t* b) {
    asm volatile("mma.sync.aligned.m16n8k32.row.col.s32.s8.s8.s32 "
        "{%0,%1,%2,%3}, {%4,%5,%6,%7}, {%8,%9}, {%0,%1,%2,%3};"
        : "+r"(c[0]), "+r"(c[1]), "+r"(c[2]), "+r"(c[3])
        : "r"(a[0]), "r"(a[1]), "r"(a[2]), "r"(a[3]), "r"(b[0]), "r"(b[1]));
}

// 512 threads: each loads one A 16B chunk and one B 16B chunk per stage
DINL void load_stage(uint32_t sb, int tm, int tn, int kt, int st, int tid) {
    uint32_t sA = sb + st * STAGE_BYTES;
    uint32_t sB = sA + 8192;
    int row = tid >> 2, w = tid & 3;
    uint32_t sw = ((w ^ ((row >> 1) & 3)) << 4);
    cp16(sA + row * 64 + sw, g_qx8 + (size_t)(tm * 128 + row) * KDIM + kt * 64 + w * 16);
    cp16(sB + row * 64 + sw, g_qk8 + (size_t)(tn * 128 + row) * KDIM + kt * 64 + w * 16);
    asm volatile("cp.async.commit_group;" ::: "memory");
}

__global__ void __launch_bounds__(512, 1) gemm8_kernel(float* __restrict__ out) {
    extern __shared__ char smem[];
    uint32_t sb = smem_u32(smem);
    int tid = threadIdx.x, lane = tid & 31, wid = tid >> 5;
    int tn = blockIdx.x & 31, tm = blockIdx.x >> 5;

    load_stage(sb, tm, tn, 0, 0, tid);
    load_stage(sb, tm, tn, 1, 1, tid);
    load_stage(sb, tm, tn, 2, 2, tid);

    if (wid < 8) {
        // ================= tensor warps: cols 0..63 =================
        int wm = wid >> 1, wn = wid & 1;
        int ct[2][4][4];
        #pragma unroll
        for (int mb = 0; mb < 2; mb++)
            #pragma unroll
            for (int nb = 0; nb < 4; nb++)
                #pragma unroll
                for (int i = 0; i < 4; i++) ct[mb][nb][i] = 0;

        int aRow0 = wm * 32 + (lane & 7) + ((lane >> 3) & 1) * 8;
        int aWsel = (lane >> 4);
        int bRow0 = wn * 32 + ((lane >> 4) << 3) + (lane & 7);
        int bWsel = ((lane >> 3) & 1);

        for (int kt = 0; kt < 64; kt++) {
            asm volatile("cp.async.wait_group %0;" :: "n"(2) : "memory");
            __syncthreads();
            if (kt + 3 < 64) load_stage(sb, tm, tn, kt + 3, (kt + 3) & 3, tid);
            uint32_t sA = sb + (kt & 3) * STAGE_BYTES;
            uint32_t sB = sA + 8192;
            #pragma unroll
            for (int ks = 0; ks < 2; ks++) {
                uint32_t a[2][4];
                #pragma unroll
                for (int mb = 0; mb < 2; mb++) {
                    int row = aRow0 + mb * 16;
                    int w = 2 * ks + aWsel;
                    ldmx4(a[mb], sA + row * 64 + ((w ^ ((row >> 1) & 3)) << 4));
                }
                uint32_t bt[4][2];
                #pragma unroll
                for (int p = 0; p < 2; p++) {
                    int nrow = bRow0 + p * 16;
                    int w = 2 * ks + bWsel;
                    uint32_t r[4];
                    ldmx4(r, sB + nrow * 64 + ((w ^ ((nrow >> 1) & 3)) << 4));
                    bt[2*p][0] = r[0]; bt[2*p][1] = r[1];
                    bt[2*p+1][0] = r[2]; bt[2*p+1][1] = r[3];
                }
                #pragma unroll
                for (int mb = 0; mb < 2; mb++)
                    #pragma unroll
                    for (int nb = 0; nb < 4; nb++)
                        mma8(ct[mb][nb], a[mb], bt[nb]);
            }
        }
        // epilogue (tensor half)
        int row0 = tm * 128 + wm * 32 + (lane >> 2);
        int ncol0 = tn * 128 + wn * 32 + (lane & 3) * 2;
        #pragma unroll
        for (int mb = 0; mb < 2; mb++) {
            #pragma unroll
            for (int half = 0; half < 2; half++) {
                int m = row0 + mb * 16 + half * 8;
                float sxv = g_sx[m];
                float* orow = out + (size_t)m * NCOLS + ncol0;
                #pragma unroll
                for (int nb = 0; nb < 4; nb++) {
                    int n0 = ncol0 + nb * 8;
                    float2 o;
                    o.x = fmaf((float)ct[mb][nb][2*half],   sxv * g_sks[n0],   g_bq[n0]);
                    o.y = fmaf((float)ct[mb][nb][2*half+1], sxv * g_sks[n0+1], g_bq[n0+1]);
                    *(float2*)(orow + nb * 8) = o;
                }
            }
        }
    } else {
        // ================= dp4a warps: cols 64..127 =================
        int dw = wid - 8;                         // 0..7
        int rBase = (dw >> 1) * 32 + (lane & 3);  // rows: + 4*i, i<8
        int cBase = 64 + (dw & 1) * 32 + (lane >> 2); // cols: + 8*j, j<4
        int cd[8][4];
        #pragma unroll
        for (int i = 0; i < 8; i++)
            #pragma unroll
            for (int j = 0; j < 4; j++) cd[i][j] = 0;

        for (int kt = 0; kt < 64; kt++) {
            asm volatile("cp.async.wait_group %0;" :: "n"(2) : "memory");
            __syncthreads();
            if (kt + 3 < 64) load_stage(sb, tm, tn, kt + 3, (kt + 3) & 3, tid);
            int sAoff = (kt & 3) * STAGE_BYTES;
            int sBoff = sAoff + 8192;
            #pragma unroll
            for (int wc = 0; wc < 4; wc++) {
                uint4 bw[4];
                #pragma unroll
                for (int j = 0; j < 4; j++) {
                    int rowB = cBase + 8 * j;
                    bw[j] = *(const uint4*)(smem + sBoff + rowB * 64
                                            + ((wc ^ ((rowB >> 1) & 3)) << 4));
                }
                #pragma unroll
                for (int i = 0; i < 8; i++) {
                    int rowA = rBase + 4 * i;
                    uint4 aw = *(const uint4*)(smem + sAoff + rowA * 64
                                               + ((wc ^ ((rowA >> 1) & 3)) << 4));
                    #pragma unroll
                    for (int j = 0; j < 4; j++) {
                        cd[i][j] = __dp4a((int)aw.x, (int)bw[j].x, cd[i][j]);
                        cd[i][j] = __dp4a((int)aw.y, (int)bw[j].y, cd[i][j]);
                        cd[i][j] = __dp4a((int)aw.z, (int)bw[j].z, cd[i][j]);
                        cd[i][j] = __dp4a((int)aw.w, (int)bw[j].w, cd[i][j]);
                    }
                }
            }
        }
        // epilogue (dp4a half)
        #pragma unroll
        for (int i = 0; i < 8; i++) {
            int m = tm * 128 + rBase + 4 * i;
            float sxv = g_sx[m];
            float* orow = out + (size_t)m * NCOLS;
            #pragma unroll
            for (int j = 0; j < 4; j++) {
                int n = tn * 128 + cBase + 8 * j;
                orow[n] = fmaf((float)cd[i][j], sxv * g_sks[n], g_bq[n]);
            }
        }
    }
}

// ---------------- output requant (in place, per-row) ----------------
__global__ void __launch_bounds__(256) requant_kernel(float* __restrict__ out) {
    __shared__ float sred[9];
    int m = blockIdx.x, t = threadIdx.x;
    float4* row = (float4*)(out + (size_t)m * NCOLS);
    float4 v[4];
    float am = 0.f;
    #pragma unroll
    for (int i = 0; i < 4; i++) {
        v[i] = row[t * 4 + i];
        am = fmaxf(am, fmaxf(fmaxf(fabsf(v[i].x), fabsf(v[i].y)),
                             fmaxf(fabsf(v[i].z), fabsf(v[i].w))));
    }
    am = blockAbsMax256(am, sred);
    float sc = (am == 0.f) ? 1.0f : __fdiv_rn(am, 127.0f);
    #pragma unroll
    for (int i = 0; i < 4; i++) {
        v[i].x = q8(v[i].x, sc) * sc;
        v[i].y = q8(v[i].y, sc) * sc;
        v[i].z = q8(v[i].z, sc) * sc;
        v[i].w = q8(v[i].w, sc) * sc;
        row[t * 4 + i] = v[i];
    }
}

extern "C" void kernel_launch(void* const* d_in, const int* in_sizes, int n_in,
                              void* d_out, int out_size) {
    const float* x    = (const float*)d_in[0];
    const float* kern = (const float*)d_in[1];
    const float* bias = (const float*)d_in[2];
    float* out = (float*)d_out;
    cudaFuncSetAttribute(gemm8_kernel, cudaFuncAttributeMaxDynamicSharedMemorySize, SMEM_TOT);
    quantX_kernel<<<MROWS + 1, 256>>>(x, bias);   // launch 1
    colmax_kernel<<<512, 256>>>(kern);            // launch 2
    quantW_kernel<<<2048, 256>>>(kern);           // launch 3
    gemm8_kernel<<<2048, 512, SMEM_TOT>>>(out);   // launch 4  (ncu -s 5 -c 1 target)
    requant_kernel<<<8192, 256>>>(out);           // launch 5
}